// round 1
// baseline (speedup 1.0000x reference)
#include <cuda_runtime.h>
#include <cuda_bf16.h>
#include <math.h>

// Problem dims (fixed by the dataset)
#define BSZ   16
#define RSZ   2048
#define DMOD  512
#define H2D   1024
#define NRELD 2048
#define MROWS (BSZ * RSZ)          // 32768

// ---------------- device scratch (static globals; allocation-free) ----------
__device__ float g_W[DMOD * DMOD];           // combined o_w @ v_w       (1 MB)
__device__ float g_c[DMOD];                  // combined bias
__device__ float g_attn[(size_t)MROWS * DMOD];   // 64 MB
__device__ float g_h[(size_t)MROWS * DMOD];      // 64 MB (LN output)
__device__ float g_t[(size_t)MROWS * H2D];       // 128 MB (relu hidden)
__device__ float g_logits[(size_t)MROWS * NRELD];// 256 MB
__device__ float g_sum[2 * MROWS];           // sum of exp(l - max) per row per step
__device__ int   g_idx[2 * MROWS];           // argmax per row per step

// ---------------- small precompute: W = o_w @ v_w, c = o_w @ v_b + o_b -----
__global__ void combine_w(const float* __restrict__ o_w,
                          const float* __restrict__ v_w,
                          float* __restrict__ W)
{
    __shared__ float Os[16][16];
    __shared__ float Vs[16][17];
    int tx = threadIdx.x, ty = threadIdx.y;
    int i = blockIdx.y * 16 + ty;
    int j = blockIdx.x * 16 + tx;
    float acc = 0.f;
    for (int k0 = 0; k0 < DMOD; k0 += 16) {
        Os[ty][tx] = o_w[i * DMOD + k0 + tx];
        Vs[ty][tx] = v_w[(k0 + ty) * DMOD + j];
        __syncthreads();
#pragma unroll
        for (int kk = 0; kk < 16; kk++) acc += Os[ty][kk] * Vs[kk][tx];
        __syncthreads();
    }
    W[i * DMOD + j] = acc;
}

__global__ void combine_c(const float* __restrict__ o_w,
                          const float* __restrict__ v_b,
                          const float* __restrict__ o_b,
                          float* __restrict__ c)
{
    int i = blockIdx.x * blockDim.x + threadIdx.x;
    if (i < DMOD) {
        float acc = o_b[i];
        for (int k = 0; k < DMOD; k++) acc += o_w[i * DMOD + k] * v_b[k];
        c[i] = acc;
    }
}

// ---------------- main tiled GEMM: C[M,N] = A[M,K] @ B[N,K]^T + bias --------
// 128x128 tile, BK=16, 256 threads, 8x8 microtile per thread.
template <bool RELU>
__global__ void __launch_bounds__(256)
gemm_tn(const float* __restrict__ A, const float* __restrict__ Bw,
        const float* __restrict__ bias, float* __restrict__ C,
        int N, int K)
{
    __shared__ float As[16][132];   // +4 pad: conflict-light stores, aligned loads
    __shared__ float Bs[16][132];

    const int tid = threadIdx.x;
    const int tx = tid & 15;        // N direction (x8)
    const int ty = tid >> 4;        // M direction (x8)
    const int mBase = blockIdx.y * 128;
    const int nBase = blockIdx.x * 128;

    const int lrow = tid >> 2;      // 0..63
    const int lc4  = tid & 3;       // which float4 of the 16-wide k slab

    float acc[8][8];
#pragma unroll
    for (int i = 0; i < 8; i++)
#pragma unroll
        for (int j = 0; j < 8; j++) acc[i][j] = 0.f;

    for (int k0 = 0; k0 < K; k0 += 16) {
#pragma unroll
        for (int it = 0; it < 2; ++it) {
            int row = lrow + it * 64;
            float4 av = *(const float4*)(A + (size_t)(mBase + row) * K + k0 + lc4 * 4);
            As[lc4 * 4 + 0][row] = av.x;
            As[lc4 * 4 + 1][row] = av.y;
            As[lc4 * 4 + 2][row] = av.z;
            As[lc4 * 4 + 3][row] = av.w;
            float4 bv = *(const float4*)(Bw + (size_t)(nBase + row) * K + k0 + lc4 * 4);
            Bs[lc4 * 4 + 0][row] = bv.x;
            Bs[lc4 * 4 + 1][row] = bv.y;
            Bs[lc4 * 4 + 2][row] = bv.z;
            Bs[lc4 * 4 + 3][row] = bv.w;
        }
        __syncthreads();
#pragma unroll
        for (int k = 0; k < 16; k++) {
            float a[8], b[8];
            *(float4*)&a[0] = *(const float4*)&As[k][ty * 8];
            *(float4*)&a[4] = *(const float4*)&As[k][ty * 8 + 4];
            *(float4*)&b[0] = *(const float4*)&Bs[k][tx * 8];
            *(float4*)&b[4] = *(const float4*)&Bs[k][tx * 8 + 4];
#pragma unroll
            for (int i = 0; i < 8; i++)
#pragma unroll
                for (int j = 0; j < 8; j++) acc[i][j] += a[i] * b[j];
        }
        __syncthreads();
    }

    float bcol[8];
#pragma unroll
    for (int j = 0; j < 8; j++) bcol[j] = bias[nBase + tx * 8 + j];

#pragma unroll
    for (int i = 0; i < 8; i++) {
        size_t crow = (size_t)(mBase + ty * 8 + i);
        float4 o0, o1;
        float v0 = acc[i][0] + bcol[0], v1 = acc[i][1] + bcol[1];
        float v2 = acc[i][2] + bcol[2], v3 = acc[i][3] + bcol[3];
        float v4 = acc[i][4] + bcol[4], v5 = acc[i][5] + bcol[5];
        float v6 = acc[i][6] + bcol[6], v7 = acc[i][7] + bcol[7];
        if (RELU) {
            v0 = fmaxf(v0, 0.f); v1 = fmaxf(v1, 0.f); v2 = fmaxf(v2, 0.f); v3 = fmaxf(v3, 0.f);
            v4 = fmaxf(v4, 0.f); v5 = fmaxf(v5, 0.f); v6 = fmaxf(v6, 0.f); v7 = fmaxf(v7, 0.f);
        }
        o0.x = v0; o0.y = v1; o0.z = v2; o0.w = v3;
        o1.x = v4; o1.y = v5; o1.z = v6; o1.w = v7;
        *(float4*)(C + crow * N + nBase + tx * 8)     = o0;
        *(float4*)(C + crow * N + nBase + tx * 8 + 4) = o1;
    }
}

// ---------------- LN over rows of (attn + state) ----------------------------
__global__ void __launch_bounds__(128)
ln_kernel(const float* __restrict__ attn, const float* __restrict__ state, int perRow,
          const float* __restrict__ g, const float* __restrict__ b,
          float* __restrict__ h)
{
    int r = blockIdx.x;
    int t = threadIdx.x;
    const float4* ar = (const float4*)(attn + (size_t)r * DMOD);
    const float4* sr = perRow ? (const float4*)(state + (size_t)r * DMOD)
                              : (const float4*)state;
    float4 a = ar[t], s = sr[t];
    float x0 = a.x + s.x, x1 = a.y + s.y, x2 = a.z + s.z, x3 = a.w + s.w;
    float sum = x0 + x1 + x2 + x3;
    float sq  = x0 * x0 + x1 * x1 + x2 * x2 + x3 * x3;
#pragma unroll
    for (int off = 16; off; off >>= 1) {
        sum += __shfl_xor_sync(0xffffffffu, sum, off);
        sq  += __shfl_xor_sync(0xffffffffu, sq, off);
    }
    __shared__ float ss[4], sv[4];
    int lane = t & 31, wid = t >> 5;
    if (lane == 0) { ss[wid] = sum; sv[wid] = sq; }
    __syncthreads();
    sum = ss[0] + ss[1] + ss[2] + ss[3];
    sq  = sv[0] + sv[1] + sv[2] + sv[3];
    float mean = sum * (1.f / DMOD);
    float rstd = rsqrtf(sq * (1.f / DMOD) - mean * mean + 1e-5f);
    float4 gv = ((const float4*)g)[t];
    float4 bv = ((const float4*)b)[t];
    float4 o;
    o.x = (x0 - mean) * rstd * gv.x + bv.x;
    o.y = (x1 - mean) * rstd * gv.y + bv.y;
    o.z = (x2 - mean) * rstd * gv.z + bv.z;
    o.w = (x3 - mean) * rstd * gv.w + bv.w;
    ((float4*)(h + (size_t)r * DMOD))[t] = o;
}

// ---------------- rowwise max / argmax / sum-exp over NREL ------------------
__global__ void __launch_bounds__(256)
softmax_stats(const float* __restrict__ logits,
              float* __restrict__ outSum, int* __restrict__ outIdx)
{
    int r = blockIdx.x;
    int t = threadIdx.x;
    const float4* row = (const float4*)(logits + (size_t)r * NRELD);
    float4 v0 = row[t];
    float4 v1 = row[t + 256];
    float vals[8] = {v0.x, v0.y, v0.z, v0.w, v1.x, v1.y, v1.z, v1.w};
    int b0 = 4 * t, b1 = 1024 + 4 * t;
    float m = vals[0]; int mi = b0;
#pragma unroll
    for (int j = 1; j < 4; j++) if (vals[j] > m) { m = vals[j]; mi = b0 + j; }
#pragma unroll
    for (int j = 0; j < 4; j++) if (vals[4 + j] > m) { m = vals[4 + j]; mi = b1 + j; }
#pragma unroll
    for (int off = 16; off; off >>= 1) {
        float vo = __shfl_xor_sync(0xffffffffu, m, off);
        int   io = __shfl_xor_sync(0xffffffffu, mi, off);
        if (vo > m || (vo == m && io < mi)) { m = vo; mi = io; }
    }
    __shared__ float wm[8]; __shared__ int wi[8];
    int lane = t & 31, wid = t >> 5;
    if (lane == 0) { wm[wid] = m; wi[wid] = mi; }
    __syncthreads();
    if (t == 0) {
#pragma unroll
        for (int w = 1; w < 8; w++)
            if (wm[w] > m || (wm[w] == m && wi[w] < mi)) { m = wm[w]; mi = wi[w]; }
        wm[0] = m; wi[0] = mi;
    }
    __syncthreads();
    float gmax = wm[0];
    float s = 0.f;
#pragma unroll
    for (int j = 0; j < 8; j++) s += expf(vals[j] - gmax);
#pragma unroll
    for (int off = 16; off; off >>= 1) s += __shfl_xor_sync(0xffffffffu, s, off);
    __shared__ float wsum[8];
    if (lane == 0) wsum[wid] = s;
    __syncthreads();
    if (t == 0) {
        float tot = 0.f;
#pragma unroll
        for (int w = 0; w < 8; w++) tot += wsum[w];
        outSum[r] = tot;       // max prob = 1 / tot
        outIdx[r] = wi[0];
    }
}

// ---------------- score / length logic + output write -----------------------
__global__ void finalize(const float* __restrict__ sum, const int* __restrict__ idx,
                         float* __restrict__ out, int out_size)
{
    int i = blockIdx.x * blockDim.x + threadIdx.x;
    if (i < MROWS) {
        float m0 = 1.0f / sum[i];
        float m1 = 1.0f / sum[MROWS + i];
        int i0 = idx[i], i1 = idx[MROWS + i];
        bool c0 = (i0 != 0) && (m0 >= 0.1f);
        bool c1 = c0 && (i1 != 0) && (m1 >= 0.1f);
        float score = c0 ? (c1 ? m0 * m1 : m0) : 0.0f;
        out[i] = score;
        if (out_size >= 4 * MROWS) {
            out[MROWS + i]     = (float)i0;
            out[2 * MROWS + i] = (float)i1;
            out[3 * MROWS + i] = (float)((int)c0 + (int)c1);
        }
    } else if (i >= 4 * MROWS && i < out_size) {
        out[i] = 0.0f;   // defensive: cover any unexpected tail
    }
}

// ---------------- launch --------------------------------------------------
extern "C" void kernel_launch(void* const* d_in, const int* in_sizes, int n_in,
                              void* d_out, int out_size)
{
    const float* x    = (const float*)d_in[0];   // rel_encoding [16,2048,512]
    const float* na   = (const float*)d_in[1];   // na_emb [512]
    const float* v_w  = (const float*)d_in[2];
    const float* v_b  = (const float*)d_in[3];
    const float* o_w  = (const float*)d_in[4];
    const float* o_b  = (const float*)d_in[5];
    const float* ln_g = (const float*)d_in[6];
    const float* ln_b = (const float*)d_in[7];
    const float* w1   = (const float*)d_in[8];   // [1024,512]
    const float* b1   = (const float*)d_in[9];
    const float* w2   = (const float*)d_in[10];  // [2048,1024]
    const float* b2   = (const float*)d_in[11];
    float* out = (float*)d_out;

    float *pW, *pc, *pattn, *ph, *pt, *plog, *psum;
    int* pidx;
    cudaGetSymbolAddress((void**)&pW,    g_W);
    cudaGetSymbolAddress((void**)&pc,    g_c);
    cudaGetSymbolAddress((void**)&pattn, g_attn);
    cudaGetSymbolAddress((void**)&ph,    g_h);
    cudaGetSymbolAddress((void**)&pt,    g_t);
    cudaGetSymbolAddress((void**)&plog,  g_logits);
    cudaGetSymbolAddress((void**)&psum,  g_sum);
    cudaGetSymbolAddress((void**)&pidx,  g_idx);

    // fold attention projections
    combine_w<<<dim3(DMOD / 16, DMOD / 16), dim3(16, 16)>>>(o_w, v_w, pW);
    combine_c<<<2, 256>>>(o_w, v_b, o_b, pc);

    // attn = x @ W^T + c
    gemm_tn<false><<<dim3(DMOD / 128, MROWS / 128), 256>>>(x, pW, pc, pattn, DMOD, DMOD);

    for (int step = 0; step < 2; step++) {
        const float* state = step ? x : na;
        ln_kernel<<<MROWS, 128>>>(pattn, state, step, ln_g, ln_b, ph);
        gemm_tn<true><<<dim3(H2D / 128, MROWS / 128), 256>>>(ph, w1, b1, pt, H2D, DMOD);
        gemm_tn<false><<<dim3(NRELD / 128, MROWS / 128), 256>>>(pt, w2, b2, plog, NRELD, H2D);
        softmax_stats<<<MROWS, 256>>>(plog, psum + step * MROWS, pidx + step * MROWS);
    }

    int total = out_size > MROWS ? out_size : MROWS;
    finalize<<<(total + 255) / 256, 256>>>(psum, pidx, out, out_size);
}

// round 3
// speedup vs baseline: 1.0538x; 1.0538x over previous
#include <cuda_runtime.h>
#include <cuda_bf16.h>
#include <math.h>

// Problem dims (fixed by the dataset)
#define BSZ   16
#define RSZ   2048
#define DMOD  512
#define H2D   1024
#define NRELD 2048
#define MROWS (BSZ * RSZ)          // 32768

// ---------------- device scratch (static globals; allocation-free) ----------
__device__ float g_W[DMOD * DMOD];           // combined o_w @ v_w       (1 MB)
__device__ float g_c[DMOD];                  // combined bias
__device__ float g_attn[(size_t)MROWS * DMOD];   // 64 MB
__device__ float g_h[(size_t)MROWS * DMOD];      // 64 MB (LN output)
__device__ float g_t[(size_t)MROWS * H2D];       // 128 MB (relu hidden)
__device__ float g_logits[(size_t)MROWS * NRELD];// 256 MB
__device__ float g_sum[2 * MROWS];           // sum of exp(l - max) per row per step
__device__ int   g_idx[2 * MROWS];           // argmax per row per step

// ---------------- small precompute: W = o_w @ v_w, c = o_w @ v_b + o_b -----
__global__ void combine_w(const float* __restrict__ o_w,
                          const float* __restrict__ v_w,
                          float* __restrict__ W)
{
    __shared__ float Os[16][16];
    __shared__ float Vs[16][17];
    int tx = threadIdx.x, ty = threadIdx.y;
    int i = blockIdx.y * 16 + ty;
    int j = blockIdx.x * 16 + tx;
    float acc = 0.f;
    for (int k0 = 0; k0 < DMOD; k0 += 16) {
        Os[ty][tx] = o_w[i * DMOD + k0 + tx];
        Vs[ty][tx] = v_w[(k0 + ty) * DMOD + j];
        __syncthreads();
#pragma unroll
        for (int kk = 0; kk < 16; kk++) acc += Os[ty][kk] * Vs[kk][tx];
        __syncthreads();
    }
    W[i * DMOD + j] = acc;
}

__global__ void combine_c(const float* __restrict__ o_w,
                          const float* __restrict__ v_b,
                          const float* __restrict__ o_b,
                          float* __restrict__ c)
{
    int i = blockIdx.x * blockDim.x + threadIdx.x;
    if (i < DMOD) {
        float acc = o_b[i];
        for (int k = 0; k < DMOD; k++) acc += o_w[i * DMOD + k] * v_b[k];
        c[i] = acc;
    }
}

// ---------------- main tiled GEMM: C[M,N] = A[M,K] @ B[N,K]^T + bias --------
// 128x128 tile, BK=16, 256 threads, 8x8 microtile per thread.
template <bool RELU>
__global__ void __launch_bounds__(256)
gemm_tn(const float* __restrict__ A, const float* __restrict__ Bw,
        const float* __restrict__ bias, float* __restrict__ C,
        int N, int K)
{
    __shared__ float As[16][132];   // +4 pad: conflict-light stores, aligned loads
    __shared__ float Bs[16][132];

    const int tid = threadIdx.x;
    const int tx = tid & 15;        // N direction (x8)
    const int ty = tid >> 4;        // M direction (x8)
    const int mBase = blockIdx.y * 128;
    const int nBase = blockIdx.x * 128;

    const int lrow = tid >> 2;      // 0..63
    const int lc4  = tid & 3;       // which float4 of the 16-wide k slab

    float acc[8][8];
#pragma unroll
    for (int i = 0; i < 8; i++)
#pragma unroll
        for (int j = 0; j < 8; j++) acc[i][j] = 0.f;

    for (int k0 = 0; k0 < K; k0 += 16) {
#pragma unroll
        for (int it = 0; it < 2; ++it) {
            int row = lrow + it * 64;
            float4 av = *(const float4*)(A + (size_t)(mBase + row) * K + k0 + lc4 * 4);
            As[lc4 * 4 + 0][row] = av.x;
            As[lc4 * 4 + 1][row] = av.y;
            As[lc4 * 4 + 2][row] = av.z;
            As[lc4 * 4 + 3][row] = av.w;
            float4 bv = *(const float4*)(Bw + (size_t)(nBase + row) * K + k0 + lc4 * 4);
            Bs[lc4 * 4 + 0][row] = bv.x;
            Bs[lc4 * 4 + 1][row] = bv.y;
            Bs[lc4 * 4 + 2][row] = bv.z;
            Bs[lc4 * 4 + 3][row] = bv.w;
        }
        __syncthreads();
#pragma unroll
        for (int k = 0; k < 16; k++) {
            float a[8], b[8];
            *(float4*)&a[0] = *(const float4*)&As[k][ty * 8];
            *(float4*)&a[4] = *(const float4*)&As[k][ty * 8 + 4];
            *(float4*)&b[0] = *(const float4*)&Bs[k][tx * 8];
            *(float4*)&b[4] = *(const float4*)&Bs[k][tx * 8 + 4];
#pragma unroll
            for (int i = 0; i < 8; i++)
#pragma unroll
                for (int j = 0; j < 8; j++) acc[i][j] += a[i] * b[j];
        }
        __syncthreads();
    }

    float bcol[8];
#pragma unroll
    for (int j = 0; j < 8; j++) bcol[j] = bias[nBase + tx * 8 + j];

#pragma unroll
    for (int i = 0; i < 8; i++) {
        size_t crow = (size_t)(mBase + ty * 8 + i);
        float4 o0, o1;
        float v0 = acc[i][0] + bcol[0], v1 = acc[i][1] + bcol[1];
        float v2 = acc[i][2] + bcol[2], v3 = acc[i][3] + bcol[3];
        float v4 = acc[i][4] + bcol[4], v5 = acc[i][5] + bcol[5];
        float v6 = acc[i][6] + bcol[6], v7 = acc[i][7] + bcol[7];
        if (RELU) {
            v0 = fmaxf(v0, 0.f); v1 = fmaxf(v1, 0.f); v2 = fmaxf(v2, 0.f); v3 = fmaxf(v3, 0.f);
            v4 = fmaxf(v4, 0.f); v5 = fmaxf(v5, 0.f); v6 = fmaxf(v6, 0.f); v7 = fmaxf(v7, 0.f);
        }
        o0.x = v0; o0.y = v1; o0.z = v2; o0.w = v3;
        o1.x = v4; o1.y = v5; o1.z = v6; o1.w = v7;
        *(float4*)(C + crow * N + nBase + tx * 8)     = o0;
        *(float4*)(C + crow * N + nBase + tx * 8 + 4) = o1;
    }
}

// ---------------- LN over rows of (attn + state) ----------------------------
__global__ void __launch_bounds__(128)
ln_kernel(const float* __restrict__ attn, const float* __restrict__ state, int perRow,
          const float* __restrict__ g, const float* __restrict__ b,
          float* __restrict__ h)
{
    int r = blockIdx.x;
    int t = threadIdx.x;
    const float4* ar = (const float4*)(attn + (size_t)r * DMOD);
    const float4* sr = perRow ? (const float4*)(state + (size_t)r * DMOD)
                              : (const float4*)state;
    float4 a = ar[t], s = sr[t];
    float x0 = a.x + s.x, x1 = a.y + s.y, x2 = a.z + s.z, x3 = a.w + s.w;
    float sum = x0 + x1 + x2 + x3;
    float sq  = x0 * x0 + x1 * x1 + x2 * x2 + x3 * x3;
#pragma unroll
    for (int off = 16; off; off >>= 1) {
        sum += __shfl_xor_sync(0xffffffffu, sum, off);
        sq  += __shfl_xor_sync(0xffffffffu, sq, off);
    }
    __shared__ float ss[4], sv[4];
    int lane = t & 31, wid = t >> 5;
    if (lane == 0) { ss[wid] = sum; sv[wid] = sq; }
    __syncthreads();
    sum = ss[0] + ss[1] + ss[2] + ss[3];
    sq  = sv[0] + sv[1] + sv[2] + sv[3];
    float mean = sum * (1.f / DMOD);
    float rstd = rsqrtf(sq * (1.f / DMOD) - mean * mean + 1e-5f);
    float4 gv = ((const float4*)g)[t];
    float4 bv = ((const float4*)b)[t];
    float4 o;
    o.x = (x0 - mean) * rstd * gv.x + bv.x;
    o.y = (x1 - mean) * rstd * gv.y + bv.y;
    o.z = (x2 - mean) * rstd * gv.z + bv.z;
    o.w = (x3 - mean) * rstd * gv.w + bv.w;
    ((float4*)(h + (size_t)r * DMOD))[t] = o;
}

// ---------------- rowwise max / argmax / sum-exp over NREL ------------------
__global__ void __launch_bounds__(256)
softmax_stats(const float* __restrict__ logits,
              float* __restrict__ outSum, int* __restrict__ outIdx)
{
    int r = blockIdx.x;
    int t = threadIdx.x;
    const float4* row = (const float4*)(logits + (size_t)r * NRELD);
    float4 v0 = row[t];
    float4 v1 = row[t + 256];
    float vals[8] = {v0.x, v0.y, v0.z, v0.w, v1.x, v1.y, v1.z, v1.w};
    int b0 = 4 * t, b1 = 1024 + 4 * t;
    float m = vals[0]; int mi = b0;
#pragma unroll
    for (int j = 1; j < 4; j++) if (vals[j] > m) { m = vals[j]; mi = b0 + j; }
#pragma unroll
    for (int j = 0; j < 4; j++) if (vals[4 + j] > m) { m = vals[4 + j]; mi = b1 + j; }
#pragma unroll
    for (int off = 16; off; off >>= 1) {
        float vo = __shfl_xor_sync(0xffffffffu, m, off);
        int   io = __shfl_xor_sync(0xffffffffu, mi, off);
        if (vo > m || (vo == m && io < mi)) { m = vo; mi = io; }
    }
    __shared__ float wm[8]; __shared__ int wi[8];
    int lane = t & 31, wid = t >> 5;
    if (lane == 0) { wm[wid] = m; wi[wid] = mi; }
    __syncthreads();
    if (t == 0) {
#pragma unroll
        for (int w = 1; w < 8; w++)
            if (wm[w] > m || (wm[w] == m && wi[w] < mi)) { m = wm[w]; mi = wi[w]; }
        wm[0] = m; wi[0] = mi;
    }
    __syncthreads();
    float gmax = wm[0];
    float s = 0.f;
#pragma unroll
    for (int j = 0; j < 8; j++) s += expf(vals[j] - gmax);
#pragma unroll
    for (int off = 16; off; off >>= 1) s += __shfl_xor_sync(0xffffffffu, s, off);
    __shared__ float wsum[8];
    if (lane == 0) wsum[wid] = s;
    __syncthreads();
    if (t == 0) {
        float tot = 0.f;
#pragma unroll
        for (int w = 0; w < 8; w++) tot += wsum[w];
        outSum[r] = tot;       // max prob = 1 / tot
        outIdx[r] = wi[0];
    }
}

// ---------------- score / length logic + output write -----------------------
__global__ void finalize(const float* __restrict__ sum, const int* __restrict__ idx,
                         float* __restrict__ out, int out_size)
{
    int i = blockIdx.x * blockDim.x + threadIdx.x;
    if (i < MROWS) {
        float m0 = 1.0f / sum[i];
        float m1 = 1.0f / sum[MROWS + i];
        int i0 = idx[i], i1 = idx[MROWS + i];
        bool c0 = (i0 != 0) && (m0 >= 0.1f);
        bool c1 = c0 && (i1 != 0) && (m1 >= 0.1f);
        float score = c0 ? (c1 ? m0 * m1 : m0) : 0.0f;
        out[i] = score;
        if (out_size >= 4 * MROWS) {
            out[MROWS + i]     = (float)i0;
            out[2 * MROWS + i] = (float)i1;
            out[3 * MROWS + i] = (float)((int)c0 + (int)c1);
        }
    } else if (i >= 4 * MROWS && i < out_size) {
        out[i] = 0.0f;   // defensive: cover any unexpected tail
    }
}

// ---------------- launch --------------------------------------------------
extern "C" void kernel_launch(void* const* d_in, const int* in_sizes, int n_in,
                              void* d_out, int out_size)
{
    const float* x    = (const float*)d_in[0];   // rel_encoding [16,2048,512]
    const float* na   = (const float*)d_in[1];   // na_emb [512]
    const float* v_w  = (const float*)d_in[2];
    const float* v_b  = (const float*)d_in[3];
    const float* o_w  = (const float*)d_in[4];
    const float* o_b  = (const float*)d_in[5];
    const float* ln_g = (const float*)d_in[6];
    const float* ln_b = (const float*)d_in[7];
    const float* w1   = (const float*)d_in[8];   // [1024,512]
    const float* b1   = (const float*)d_in[9];
    const float* w2   = (const float*)d_in[10];  // [2048,1024]
    const float* b2   = (const float*)d_in[11];
    float* out = (float*)d_out;

    float *pW, *pc, *pattn, *ph, *pt, *plog, *psum;
    int* pidx;
    cudaGetSymbolAddress((void**)&pW,    g_W);
    cudaGetSymbolAddress((void**)&pc,    g_c);
    cudaGetSymbolAddress((void**)&pattn, g_attn);
    cudaGetSymbolAddress((void**)&ph,    g_h);
    cudaGetSymbolAddress((void**)&pt,    g_t);
    cudaGetSymbolAddress((void**)&plog,  g_logits);
    cudaGetSymbolAddress((void**)&psum,  g_sum);
    cudaGetSymbolAddress((void**)&pidx,  g_idx);

    // fold attention projections
    combine_w<<<dim3(DMOD / 16, DMOD / 16), dim3(16, 16)>>>(o_w, v_w, pW);
    combine_c<<<2, 256>>>(o_w, v_b, o_b, pc);

    // attn = x @ W^T + c
    gemm_tn<false><<<dim3(DMOD / 128, MROWS / 128), 256>>>(x, pW, pc, pattn, DMOD, DMOD);

    for (int step = 0; step < 2; step++) {
        const float* state = step ? x : na;
        ln_kernel<<<MROWS, 128>>>(pattn, state, step, ln_g, ln_b, ph);
        gemm_tn<true><<<dim3(H2D / 128, MROWS / 128), 256>>>(ph, w1, b1, pt, H2D, DMOD);
        gemm_tn<false><<<dim3(NRELD / 128, MROWS / 128), 256>>>(pt, w2, b2, plog, NRELD, H2D);
        softmax_stats<<<MROWS, 256>>>(plog, psum + step * MROWS, pidx + step * MROWS);
    }

    int total = out_size > MROWS ? out_size : MROWS;
    finalize<<<(total + 255) / 256, 256>>>(psum, pidx, out, out_size);
}

// round 6
// speedup vs baseline: 2.9572x; 2.8061x over previous
#include <cuda_runtime.h>
#include <cuda_bf16.h>
#include <math.h>
#include <stdint.h>

#define BSZ   16
#define RSZ   2048
#define DMOD  512
#define H2D   1024
#define NRELD 2048
#define MROWS (BSZ * RSZ)          // 32768
#define MARGIN 0.025f

// ===================== device scratch (allocation-free) =====================
__device__ __align__(256) float g_W[DMOD * DMOD];
__device__ __align__(256) float g_c[DMOD];
__device__ __align__(256) float g_attn[(size_t)MROWS * DMOD];
__device__ __align__(256) __nv_bfloat16 g_x0[(size_t)MROWS * DMOD];
__device__ __align__(256) __nv_bfloat16 g_x1[(size_t)MROWS * DMOD];
__device__ __align__(256) __nv_bfloat16 g_x2[(size_t)MROWS * DMOD];
__device__ __align__(256) __nv_bfloat16 g_h0[(size_t)MROWS * DMOD];
__device__ __align__(256) __nv_bfloat16 g_h1[(size_t)MROWS * DMOD];
__device__ __align__(256) __nv_bfloat16 g_h2[(size_t)MROWS * DMOD];
__device__ __align__(256) float g_tf[(size_t)MROWS * H2D];          // fp32 hidden
__device__ __align__(256) __nv_bfloat16 g_tb[(size_t)MROWS * H2D]; // bf16 hidden
__device__ __align__(256) __nv_bfloat16 g_Ws0[DMOD * DMOD];
__device__ __align__(256) __nv_bfloat16 g_Ws1[DMOD * DMOD];
__device__ __align__(256) __nv_bfloat16 g_Ws2[DMOD * DMOD];
__device__ __align__(256) __nv_bfloat16 g_w1s0[H2D * DMOD];
__device__ __align__(256) __nv_bfloat16 g_w1s1[H2D * DMOD];
__device__ __align__(256) __nv_bfloat16 g_w1s2[H2D * DMOD];
__device__ __align__(256) __nv_bfloat16 g_w2b[(size_t)NRELD * H2D];
__device__ __align__(256) float g_logits[(size_t)MROWS * NRELD];
__device__ __align__(256) float g_m[2 * MROWS];
__device__ __align__(256) int   g_i[2 * MROWS];

// ===================== helpers ==============================================
__device__ __forceinline__ uint32_t smem_u32(const void* p) {
    uint32_t a;
    asm("{ .reg .u64 t; cvta.to.shared.u64 t, %1; cvt.u32.u64 %0, t; }" : "=r"(a) : "l"(p));
    return a;
}
__device__ __forceinline__ void split3(float v, __nv_bfloat16& b0, __nv_bfloat16& b1,
                                       __nv_bfloat16& b2) {
    b0 = __float2bfloat16(v);
    float r = v - __bfloat162float(b0);
    b1 = __float2bfloat16(r);
    b2 = __float2bfloat16(r - __bfloat162float(b1));
}
__device__ __forceinline__ uint32_t pack2(__nv_bfloat16 lo, __nv_bfloat16 hi) {
    __nv_bfloat162 t; t.x = lo; t.y = hi;
    return *reinterpret_cast<uint32_t*>(&t);
}

#define CP_ASYNC16(dst, src) \
    asm volatile("cp.async.cg.shared.global [%0], [%1], 16;" :: "r"(dst), "l"(src) : "memory")
#define CP_COMMIT() asm volatile("cp.async.commit_group;" ::: "memory")

#define LDSM4(r0, r1, r2, r3, addr) \
    asm volatile("ldmatrix.sync.aligned.m8n8.x4.shared.b16 {%0,%1,%2,%3}, [%4];" \
                 : "=r"(r0), "=r"(r1), "=r"(r2), "=r"(r3) : "r"(addr))
#define LDSM2(r0, r1, addr) \
    asm volatile("ldmatrix.sync.aligned.m8n8.x2.shared.b16 {%0,%1}, [%2];" \
                 : "=r"(r0), "=r"(r1) : "r"(addr))
#define MMA16816(c, a, b) \
    asm volatile("mma.sync.aligned.m16n8k16.row.col.f32.bf16.bf16.f32 " \
                 "{%0,%1,%2,%3}, {%4,%5,%6,%7}, {%8,%9}, {%0,%1,%2,%3};" \
                 : "+f"((c)[0]), "+f"((c)[1]), "+f"((c)[2]), "+f"((c)[3]) \
                 : "r"((a)[0]), "r"((a)[1]), "r"((a)[2]), "r"((a)[3]), \
                   "r"((b)[0]), "r"((b)[1]))

// ===================== mma.sync GEMM ========================================
// C[M,N] = sum_p A_p @ B_p^T (+bias), A[M,K] row-major, B[N,K] row-major.
// BM=128, BN=128, BK=32, 8 warps (2x4), warp tile 64x32, m16n8k16.
// EPI 0: store fp32 (Of).  EPI 1: relu -> store fp32 (Of) AND bf16 (Ob).
#define BMm 128
#define BNm 128
#define ASTR 40                      // smem row stride (elements) -> 80B rows
#define ABUFB (BMm * ASTR * 2)       // bytes per buffer

template <int EPI>
__global__ void __launch_bounds__(256, 2)
mma_gemm(const __nv_bfloat16* __restrict__ A0, const __nv_bfloat16* __restrict__ A1,
         const __nv_bfloat16* __restrict__ A2,
         const __nv_bfloat16* __restrict__ B0, const __nv_bfloat16* __restrict__ B1,
         const __nv_bfloat16* __restrict__ B2,
         const float* __restrict__ bias, int K, int Ntot, int P,
         float* __restrict__ Of, __nv_bfloat16* __restrict__ Ob)
{
    __shared__ __align__(16) __nv_bfloat16 As[2][BMm * ASTR];
    __shared__ __align__(16) __nv_bfloat16 Bs[2][BNm * ASTR];
    __shared__ __align__(16) float biasS[BNm];

    const int tid = threadIdx.x;
    const int mBase = blockIdx.y * BMm;
    const int nBase = blockIdx.x * BNm;
    if (tid < BNm) biasS[tid] = bias[nBase + tid];

    const __nv_bfloat16* AL[3] = {A0, A1, A2};
    const __nv_bfloat16* BL[3] = {B0, B1, B2};
    const int AI[6] = {0, 1, 0, 2, 1, 0};
    const int BI[6] = {0, 0, 1, 0, 1, 2};
    const int KC = K >> 5;           // k-chunks of 32
    const int S = P * KC;

    const uint32_t aBase = smem_u32(As);
    const uint32_t bBase = smem_u32(Bs);

    int lp = 0, lkc = 0;             // load cursor
    auto load_stage = [&](int buf) {
        const __nv_bfloat16* Ap = AL[AI[lp]];
        const __nv_bfloat16* Bp = BL[BI[lp]];
        int k0 = lkc << 5;
#pragma unroll
        for (int i = 0; i < 2; i++) {
            int c = tid + (i << 8);          // 0..511
            int row = c >> 2, kc = c & 3;
            CP_ASYNC16(aBase + (uint32_t)buf * ABUFB + (uint32_t)(row * ASTR + kc * 8) * 2,
                       Ap + (size_t)(mBase + row) * K + k0 + kc * 8);
            CP_ASYNC16(bBase + (uint32_t)buf * ABUFB + (uint32_t)(row * ASTR + kc * 8) * 2,
                       Bp + (size_t)(nBase + row) * K + k0 + kc * 8);
        }
        CP_COMMIT();
        if (++lkc == KC) { lkc = 0; ++lp; }
    };

    float acc[4][4][4];
#pragma unroll
    for (int mi = 0; mi < 4; mi++)
#pragma unroll
        for (int ni = 0; ni < 4; ni++)
#pragma unroll
            for (int q = 0; q < 4; q++) acc[mi][ni][q] = 0.f;

    const int lane = tid & 31;
    const int warp = tid >> 5;
    const int wm = (warp >> 2) * 64;       // 0 or 64
    const int wn = (warp & 3) * 32;
    const int arow = wm + (lane & 15);
    const int acol = (lane >> 4) << 3;
    const int brow = wn + (lane & 7);
    const int bcol = ((lane >> 3) & 1) << 3;

    load_stage(0);
    load_stage(1);

    for (int s = 0; s < S; s++) {
        if (s + 1 < S) { asm volatile("cp.async.wait_group 1;" ::: "memory"); }
        else           { asm volatile("cp.async.wait_group 0;" ::: "memory"); }
        __syncthreads();
        const uint32_t aB = aBase + (uint32_t)(s & 1) * ABUFB;
        const uint32_t bB = bBase + (uint32_t)(s & 1) * ABUFB;
#pragma unroll
        for (int k16 = 0; k16 < 2; k16++) {
            uint32_t a[4][4], b[4][2];
#pragma unroll
            for (int mi = 0; mi < 4; mi++)
                LDSM4(a[mi][0], a[mi][1], a[mi][2], a[mi][3],
                      aB + (uint32_t)((arow + mi * 16) * ASTR + k16 * 16 + acol) * 2);
#pragma unroll
            for (int ni = 0; ni < 4; ni++)
                LDSM2(b[ni][0], b[ni][1],
                      bB + (uint32_t)((brow + ni * 8) * ASTR + k16 * 16 + bcol) * 2);
#pragma unroll
            for (int mi = 0; mi < 4; mi++)
#pragma unroll
                for (int ni = 0; ni < 4; ni++)
                    MMA16816(acc[mi][ni], a[mi], b[ni]);
        }
        __syncthreads();
        if (s + 2 < S) load_stage(s & 1);  // refill the buffer just consumed
    }

    // -------- epilogue --------
    const int r0 = mBase + wm + (lane >> 2);
    const int c0 = wn + (lane & 3) * 2;
#pragma unroll
    for (int mi = 0; mi < 4; mi++) {
#pragma unroll
        for (int ni = 0; ni < 4; ni++) {
            int cc = c0 + ni * 8;
            float bx = biasS[cc], by = biasS[cc + 1];
            float v0 = acc[mi][ni][0] + bx, v1 = acc[mi][ni][1] + by;
            float v2 = acc[mi][ni][2] + bx, v3 = acc[mi][ni][3] + by;
            if (EPI == 1) {
                v0 = fmaxf(v0, 0.f); v1 = fmaxf(v1, 0.f);
                v2 = fmaxf(v2, 0.f); v3 = fmaxf(v3, 0.f);
            }
            size_t ra = (size_t)(r0 + mi * 16) * Ntot + nBase + cc;
            size_t rb = ra + (size_t)8 * Ntot;
            *(float2*)(Of + ra) = make_float2(v0, v1);
            *(float2*)(Of + rb) = make_float2(v2, v3);
            if (EPI == 1) {
                *(uint32_t*)(Ob + ra) = pack2(__float2bfloat16(v0), __float2bfloat16(v1));
                *(uint32_t*)(Ob + rb) = pack2(__float2bfloat16(v2), __float2bfloat16(v3));
            }
        }
    }
}

// ===================== precompute kernels ===================================
__global__ void combine_w(const float* __restrict__ o_w, const float* __restrict__ v_w,
                          float* __restrict__ W)
{
    __shared__ float Os[16][16];
    __shared__ float Vs[16][17];
    int tx = threadIdx.x, ty = threadIdx.y;
    int i = blockIdx.y * 16 + ty;
    int j = blockIdx.x * 16 + tx;
    float acc = 0.f;
    for (int k0 = 0; k0 < DMOD; k0 += 16) {
        Os[ty][tx] = o_w[i * DMOD + k0 + tx];
        Vs[ty][tx] = v_w[(k0 + ty) * DMOD + j];
        __syncthreads();
#pragma unroll
        for (int kk = 0; kk < 16; kk++) acc += Os[ty][kk] * Vs[kk][tx];
        __syncthreads();
    }
    W[i * DMOD + j] = acc;
}

__global__ void combine_c(const float* __restrict__ o_w, const float* __restrict__ v_b,
                          const float* __restrict__ o_b, float* __restrict__ c)
{
    int i = blockIdx.x * blockDim.x + threadIdx.x;
    if (i < DMOD) {
        float acc = o_b[i];
        for (int k = 0; k < DMOD; k++) acc += o_w[i * DMOD + k] * v_b[k];
        c[i] = acc;
    }
}

__global__ void split_all(const float* __restrict__ src, __nv_bfloat16* __restrict__ d0,
                          __nv_bfloat16* __restrict__ d1, __nv_bfloat16* __restrict__ d2,
                          int n4)
{
    int i = blockIdx.x * blockDim.x + threadIdx.x;
    if (i >= n4) return;
    float4 v = ((const float4*)src)[i];
    __nv_bfloat16 a0, a1, a2, b0, b1, b2, c0, c1, c2, e0, e1, e2;
    split3(v.x, a0, a1, a2);
    split3(v.y, b0, b1, b2);
    split3(v.z, c0, c1, c2);
    split3(v.w, e0, e1, e2);
    uint2 u0, u1, u2;
    u0.x = pack2(a0, b0); u0.y = pack2(c0, e0);
    u1.x = pack2(a1, b1); u1.y = pack2(c1, e1);
    u2.x = pack2(a2, b2); u2.y = pack2(c2, e2);
    ((uint2*)d0)[i] = u0;
    ((uint2*)d1)[i] = u1;
    ((uint2*)d2)[i] = u2;
}

__global__ void conv_bf16(const float* __restrict__ src, __nv_bfloat16* __restrict__ dst,
                          int n4)
{
    int i = blockIdx.x * blockDim.x + threadIdx.x;
    if (i >= n4) return;
    float4 v = ((const float4*)src)[i];
    uint2 u;
    u.x = pack2(__float2bfloat16(v.x), __float2bfloat16(v.y));
    u.y = pack2(__float2bfloat16(v.z), __float2bfloat16(v.w));
    ((uint2*)dst)[i] = u;
}

// ===================== LN (attn+state) -> 3-way bf16 split ==================
__global__ void __launch_bounds__(128)
ln_split(const float* __restrict__ attn, const float* __restrict__ state, int perRow,
         const float* __restrict__ g, const float* __restrict__ b,
         __nv_bfloat16* __restrict__ h0, __nv_bfloat16* __restrict__ h1,
         __nv_bfloat16* __restrict__ h2)
{
    int r = blockIdx.x;
    int t = threadIdx.x;
    const float4* ar = (const float4*)(attn + (size_t)r * DMOD);
    const float4* sr = perRow ? (const float4*)(state + (size_t)r * DMOD)
                              : (const float4*)state;
    float4 a = ar[t], s = sr[t];
    float x0 = a.x + s.x, x1 = a.y + s.y, x2 = a.z + s.z, x3 = a.w + s.w;
    float sum = x0 + x1 + x2 + x3;
    float sq = x0 * x0 + x1 * x1 + x2 * x2 + x3 * x3;
#pragma unroll
    for (int off = 16; off; off >>= 1) {
        sum += __shfl_xor_sync(0xffffffffu, sum, off);
        sq  += __shfl_xor_sync(0xffffffffu, sq, off);
    }
    __shared__ float ss[4], sv[4];
    int lane = t & 31, wq = t >> 5;
    if (lane == 0) { ss[wq] = sum; sv[wq] = sq; }
    __syncthreads();
    sum = ss[0] + ss[1] + ss[2] + ss[3];
    sq  = sv[0] + sv[1] + sv[2] + sv[3];
    float mean = sum * (1.f / DMOD);
    float rstd = rsqrtf(sq * (1.f / DMOD) - mean * mean + 1e-5f);
    float4 gv = ((const float4*)g)[t];
    float4 bv = ((const float4*)b)[t];
    float o0 = (x0 - mean) * rstd * gv.x + bv.x;
    float o1 = (x1 - mean) * rstd * gv.y + bv.y;
    float o2 = (x2 - mean) * rstd * gv.z + bv.z;
    float o3 = (x3 - mean) * rstd * gv.w + bv.w;
    __nv_bfloat16 a0, a1, a2, b0, b1, b2, c0, c1, c2, e0, e1, e2;
    split3(o0, a0, a1, a2);
    split3(o1, b0, b1, b2);
    split3(o2, c0, c1, c2);
    split3(o3, e0, e1, e2);
    uint2 u0, u1, u2;
    u0.x = pack2(a0, b0); u0.y = pack2(c0, e0);
    u1.x = pack2(a1, b1); u1.y = pack2(c1, e1);
    u2.x = pack2(a2, b2); u2.y = pack2(c2, e2);
    ((uint2*)(h0 + (size_t)r * DMOD))[t] = u0;
    ((uint2*)(h1 + (size_t)r * DMOD))[t] = u1;
    ((uint2*)(h2 + (size_t)r * DMOD))[t] = u2;
}

// ===================== stats + exact argmax rescue ==========================
// Per row: approx max M + sumexp from fp32 logits (bf16-mma accuracy), then
// exact fp32 dot for every candidate within MARGIN of M. Deterministic:
// winner chosen by strict (value, lowest-index) compare, order-invariant.
__global__ void __launch_bounds__(256)
stats_rescue(const float* __restrict__ logits, const float* __restrict__ tf,
             const float* __restrict__ w2, const float* __restrict__ b2,
             float* __restrict__ mOut, int* __restrict__ iOut)
{
    int r = blockIdx.x;
    int t = threadIdx.x;
    const int lane = t & 31, wq = t >> 5;
    const float4* Lr = (const float4*)(logits + (size_t)r * NRELD);
    float4 u0 = Lr[t], u1 = Lr[t + 256];
    float v[8] = {u0.x, u0.y, u0.z, u0.w, u1.x, u1.y, u1.z, u1.w};

    // block max (approx)
    float m = v[0];
#pragma unroll
    for (int j = 1; j < 8; j++) m = fmaxf(m, v[j]);
#pragma unroll
    for (int off = 16; off; off >>= 1) m = fmaxf(m, __shfl_xor_sync(0xffffffffu, m, off));
    __shared__ float wmax[8];
    if (lane == 0) wmax[wq] = m;
    __syncthreads();
    float M = wmax[0];
#pragma unroll
    for (int w = 1; w < 8; w++) M = fmaxf(M, wmax[w]);

    // sumexp (approx; probs face the 0.1 threshold with ~26 sigma margin)
    float s = 0.f;
#pragma unroll
    for (int j = 0; j < 8; j++) s += __expf(v[j] - M);
#pragma unroll
    for (int off = 16; off; off >>= 1) s += __shfl_xor_sync(0xffffffffu, s, off);
    __shared__ float wsum[8];
    if (lane == 0) wsum[wq] = s;
    __syncthreads();

    // candidate collection
    __shared__ int cnt;
    __shared__ int list[256];
    if (t == 0) cnt = 0;
    __syncthreads();
#pragma unroll
    for (int j = 0; j < 8; j++) {
        if (v[j] >= M - MARGIN) {
            int p = atomicAdd(&cnt, 1);
            if (p < 256) list[p] = (j < 4) ? (4 * t + j) : (1024 + 4 * t + j - 4);
        }
    }
    // stage t row (16B-aligned shared buffer: read as float4 below)
    __shared__ __align__(16) float ts[H2D];
    ((float4*)ts)[t] = ((const float4*)(tf + (size_t)r * H2D))[t];
    __syncthreads();
    int C = cnt < 256 ? cnt : 256;

    __shared__ float red[8];
    __shared__ float bestV_s;
    __shared__ int bestI_s;
    if (t == 0) { bestV_s = -1e30f; bestI_s = 0x7fffffff; }
    __syncthreads();
    for (int c = 0; c < C; c++) {
        int j = list[c];
        const float4* wr = (const float4*)(w2 + (size_t)j * H2D);
        float4 w = wr[t];
        float4 tv = ((const float4*)ts)[t];
        float d = w.x * tv.x + w.y * tv.y + w.z * tv.z + w.w * tv.w;
#pragma unroll
        for (int off = 16; off; off >>= 1) d += __shfl_xor_sync(0xffffffffu, d, off);
        if (lane == 0) red[wq] = d;
        __syncthreads();
        if (t == 0) {
            float tot = b2[j];
#pragma unroll
            for (int w8 = 0; w8 < 8; w8++) tot += red[w8];
            if (tot > bestV_s || (tot == bestV_s && j < bestI_s)) { bestV_s = tot; bestI_s = j; }
        }
        __syncthreads();
    }
    if (t == 0) {
        float S = 0.f;
#pragma unroll
        for (int w8 = 0; w8 < 8; w8++) S += wsum[w8];
        mOut[r] = __expf(bestV_s - M) / S;
        iOut[r] = bestI_s;
    }
}

// ===================== finalize =============================================
__global__ void finalize(const float* __restrict__ m, const int* __restrict__ idx,
                         float* __restrict__ out, int out_size)
{
    int i = blockIdx.x * blockDim.x + threadIdx.x;
    if (i < MROWS) {
        float m0 = m[i], m1 = m[MROWS + i];
        int i0 = idx[i], i1 = idx[MROWS + i];
        bool c0 = (i0 != 0) && (m0 >= 0.1f);
        bool c1 = c0 && (i1 != 0) && (m1 >= 0.1f);
        float score = c0 ? (c1 ? m0 * m1 : m0) : 0.0f;
        out[i] = score;
        if (out_size >= 4 * MROWS) {
            out[MROWS + i]     = (float)i0;
            out[2 * MROWS + i] = (float)i1;
            out[3 * MROWS + i] = (float)((int)c0 + (int)c1);
        }
    } else if (i >= 4 * MROWS && i < out_size) {
        out[i] = 0.0f;
    }
}

// ===================== launch ===============================================
extern "C" void kernel_launch(void* const* d_in, const int* in_sizes, int n_in,
                              void* d_out, int out_size)
{
    const float* x    = (const float*)d_in[0];
    const float* na   = (const float*)d_in[1];
    const float* v_w  = (const float*)d_in[2];
    const float* v_b  = (const float*)d_in[3];
    const float* o_w  = (const float*)d_in[4];
    const float* o_b  = (const float*)d_in[5];
    const float* ln_g = (const float*)d_in[6];
    const float* ln_b = (const float*)d_in[7];
    const float* w1   = (const float*)d_in[8];
    const float* b1   = (const float*)d_in[9];
    const float* w2   = (const float*)d_in[10];
    const float* b2   = (const float*)d_in[11];
    float* out = (float*)d_out;

    float *pW, *pc, *pattn, *ptf, *plog, *pm;
    __nv_bfloat16 *px0, *px1, *px2, *ph0, *ph1, *ph2, *ptb;
    __nv_bfloat16 *pWs0, *pWs1, *pWs2, *pw1s0, *pw1s1, *pw1s2, *pw2b;
    int* pi;
    cudaGetSymbolAddress((void**)&pW, g_W);
    cudaGetSymbolAddress((void**)&pc, g_c);
    cudaGetSymbolAddress((void**)&pattn, g_attn);
    cudaGetSymbolAddress((void**)&px0, g_x0);
    cudaGetSymbolAddress((void**)&px1, g_x1);
    cudaGetSymbolAddress((void**)&px2, g_x2);
    cudaGetSymbolAddress((void**)&ph0, g_h0);
    cudaGetSymbolAddress((void**)&ph1, g_h1);
    cudaGetSymbolAddress((void**)&ph2, g_h2);
    cudaGetSymbolAddress((void**)&ptf, g_tf);
    cudaGetSymbolAddress((void**)&ptb, g_tb);
    cudaGetSymbolAddress((void**)&pWs0, g_Ws0);
    cudaGetSymbolAddress((void**)&pWs1, g_Ws1);
    cudaGetSymbolAddress((void**)&pWs2, g_Ws2);
    cudaGetSymbolAddress((void**)&pw1s0, g_w1s0);
    cudaGetSymbolAddress((void**)&pw1s1, g_w1s1);
    cudaGetSymbolAddress((void**)&pw1s2, g_w1s2);
    cudaGetSymbolAddress((void**)&pw2b, g_w2b);
    cudaGetSymbolAddress((void**)&plog, g_logits);
    cudaGetSymbolAddress((void**)&pm, g_m);
    cudaGetSymbolAddress((void**)&pi, g_i);

    // fold attention projections; split operands
    combine_w<<<dim3(DMOD / 16, DMOD / 16), dim3(16, 16)>>>(o_w, v_w, pW);
    combine_c<<<2, 256>>>(o_w, v_b, o_b, pc);
    split_all<<<(MROWS * DMOD / 4 + 255) / 256, 256>>>(x, px0, px1, px2, MROWS * DMOD / 4);
    split_all<<<(DMOD * DMOD / 4 + 255) / 256, 256>>>(pW, pWs0, pWs1, pWs2, DMOD * DMOD / 4);
    split_all<<<(H2D * DMOD / 4 + 255) / 256, 256>>>(w1, pw1s0, pw1s1, pw1s2, H2D * DMOD / 4);
    conv_bf16<<<(NRELD * H2D / 4 + 255) / 256, 256>>>(w2, pw2b, NRELD * H2D / 4);

    // attn = x @ W^T + c   (split-3, fp32 out)
    mma_gemm<0><<<dim3(DMOD / BNm, MROWS / BMm), 256>>>(
        px0, px1, px2, pWs0, pWs1, pWs2, pc, DMOD, DMOD, 6, pattn, nullptr);

    for (int step = 0; step < 2; step++) {
        const float* state = step ? x : na;
        ln_split<<<MROWS, 128>>>(pattn, state, step, ln_g, ln_b, ph0, ph1, ph2);
        // t = relu(h @ w1^T + b1)  (split-3 -> fp32 + bf16)
        mma_gemm<1><<<dim3(H2D / BNm, MROWS / BMm), 256>>>(
            ph0, ph1, ph2, pw1s0, pw1s1, pw1s2, b1, DMOD, H2D, 6, ptf, ptb);
        // logits = t @ w2^T + b2  (plain bf16 -> fp32 logits)
        mma_gemm<0><<<dim3(NRELD / BNm, MROWS / BMm), 256>>>(
            ptb, ptb, ptb, pw2b, pw2b, pw2b, b2, H2D, NRELD, 1, plog, nullptr);
        // exact argmax rescue + stats
        stats_rescue<<<MROWS, 256>>>(plog, ptf, w2, b2,
                                     pm + step * MROWS, pi + step * MROWS);
    }

    int total = out_size > MROWS ? out_size : MROWS;
    finalize<<<(total + 255) / 256, 256>>>(pm, pi, out, out_size);
}